// round 11
// baseline (speedup 1.0000x reference)
#include <cuda_runtime.h>
#include <math.h>

#define T_TOK 2048
#define NE 8
#define TOPK 2
#define HD 2048
#define ID 1408
#define ISD 5632
#define NSLOT (T_TOK * TOPK)          // 4096 compact routed rows

#define BM 128
#define BN 64
#define BK 16
#define SSTR 20   // smem row stride in floats (16 + 4 pad)

#define WSLOT 23068672                 // floats: NE*ID*HD (largest weight tensor)

// ---------------- scratch (static device globals; ~212 MB total) -------------
__device__ float d_Hs[(size_t)T_TOK * ISD];      // 46.1 MB shared hidden (g, then silu*u)
__device__ float d_Hr[(size_t)NSLOT * ID];       // 23.1 MB routed hidden (compact)
__device__ float d_Y [(size_t)NSLOT * HD];       // 33.5 MB routed down output
__device__ float d_xr[(size_t)T_TOK * HD];       // 16.8 MB tf32-rounded activations
__device__ float d_Wr[(size_t)WSLOT];            // 92.3 MB weight scratch (one slot)
__device__ int   d_tok[NE * T_TOK];
__device__ float d_wt [NE * T_TOK];
__device__ int   d_cnt[NE];
__device__ int   d_off[NE];                      // global row offset per expert
__device__ int   d_slot[T_TOK * TOPK];           // token,k -> compact row in d_Y
__device__ int   d_topki[T_TOK * TOPK];
__device__ float d_topkw[T_TOK * TOPK];

// ---------------- small PTX helpers ------------------------------------------
__device__ __forceinline__ unsigned smem_u32(const void* p) {
    return (unsigned)__cvta_generic_to_shared(p);
}
__device__ __forceinline__ void cp16(unsigned dst, const void* src) {
    asm volatile("cp.async.cg.shared.global [%0], [%1], 16;\n" :: "r"(dst), "l"(src));
}
__device__ __forceinline__ void cp_commit() { asm volatile("cp.async.commit_group;\n"); }
template <int N>
__device__ __forceinline__ void cp_wait() { asm volatile("cp.async.wait_group %0;\n" :: "n"(N)); }
__device__ __forceinline__ unsigned f2tf(float f) {
    unsigned r; asm("cvt.rna.tf32.f32 %0, %1;" : "=r"(r) : "f"(f)); return r;
}
// operands pre-rounded to tf32-RNA: raw f32 bits, hardware truncation is exact
__device__ __forceinline__ void mma1688(float c[4], const unsigned a[4], const unsigned b[2]) {
    asm volatile(
        "mma.sync.aligned.m16n8k8.row.col.f32.tf32.tf32.f32 "
        "{%0,%1,%2,%3},{%4,%5,%6,%7},{%8,%9},{%0,%1,%2,%3};\n"
        : "+f"(c[0]), "+f"(c[1]), "+f"(c[2]), "+f"(c[3])
        : "r"(a[0]), "r"(a[1]), "r"(a[2]), "r"(a[3]), "r"(b[0]), "r"(b[1]));
}
__device__ __forceinline__ float silu_mul(float g, float u) {
    return g / (1.f + expf(-g)) * u;
}

// ---------------- tf32 pre-round (RNA): SLOT 0 -> d_Wr, 1 -> d_xr -------------
template <int SLOT>
__global__ void round_k(const float4* __restrict__ src, int n4)
{
    int i = blockIdx.x * blockDim.x + threadIdx.x;
    if (i >= n4) return;
    float4 v = src[i], o;
    o.x = __uint_as_float(f2tf(v.x));
    o.y = __uint_as_float(f2tf(v.y));
    o.z = __uint_as_float(f2tf(v.z));
    o.w = __uint_as_float(f2tf(v.w));
    float4* dst = (SLOT == 0) ? (float4*)d_Wr : (float4*)d_xr;
    dst[i] = o;
}

// ---------------- routing (exact fp32 x) --------------------------------------
__global__ void route_kernel(const float* __restrict__ x, const float* __restrict__ gw)
{
    int warp = (blockIdx.x * blockDim.x + threadIdx.x) >> 5;
    int lane = threadIdx.x & 31;
    if (warp >= T_TOK) return;
    const float* xr = x + (size_t)warp * HD;

    float s[NE];
#pragma unroll
    for (int e = 0; e < NE; e++) s[e] = 0.f;
    for (int k = lane; k < HD; k += 32) {
        float xv = xr[k];
#pragma unroll
        for (int e = 0; e < NE; e++) s[e] += xv * gw[e * HD + k];
    }
#pragma unroll
    for (int e = 0; e < NE; e++)
#pragma unroll
        for (int off = 16; off; off >>= 1)
            s[e] += __shfl_down_sync(0xffffffffu, s[e], off);

    if (lane == 0) {
        float mx = s[0];
#pragma unroll
        for (int e = 1; e < NE; e++) mx = fmaxf(mx, s[e]);
        float g[NE], sum = 0.f;
#pragma unroll
        for (int e = 0; e < NE; e++) { g[e] = expf(s[e] - mx); sum += g[e]; }
        float inv = 1.f / sum;
#pragma unroll
        for (int e = 0; e < NE; e++) g[e] *= inv;
        int i0 = 0; float v0 = g[0];
#pragma unroll
        for (int e = 1; e < NE; e++) if (g[e] > v0) { v0 = g[e]; i0 = e; }
        int i1 = -1; float v1 = -1.f;
#pragma unroll
        for (int e = 0; e < NE; e++) if (e != i0 && g[e] > v1) { v1 = g[e]; i1 = e; }
        float dn = 1.f / (v0 + v1);
        d_topki[warp * 2 + 0] = i0;  d_topkw[warp * 2 + 0] = v0 * dn;
        d_topki[warp * 2 + 1] = i1;  d_topkw[warp * 2 + 1] = v1 * dn;
    }
}

// ------- deterministic compaction with global (cross-expert) offsets ----------
__global__ void build_kernel()
{
    int e = blockIdx.x;
    int tid = threadIdx.x;
    int lane = tid & 31, w = tid >> 5;
    __shared__ int warp_sums[8];
    __shared__ int s_base;
    __shared__ int s_off;

    // pass 0: off[e] = number of assignments to experts < e
    int cl = 0;
    for (int j = tid; j < T_TOK * TOPK; j += 256) cl += (d_topki[j] < e) ? 1 : 0;
#pragma unroll
    for (int o = 16; o; o >>= 1) cl += __shfl_down_sync(0xffffffffu, cl, o);
    if (lane == 0) warp_sums[w] = cl;
    __syncthreads();
    if (tid == 0) {
        int t = 0;
        for (int i = 0; i < 8; i++) t += warp_sums[i];
        s_off = t; s_base = 0; d_off[e] = t;
    }
    __syncthreads();

    // pass 1: compaction
    for (int c = 0; c < T_TOK; c += 256) {
        int t = c + tid;
        int k = -1;
        if (d_topki[2 * t] == e) k = 0;
        else if (d_topki[2 * t + 1] == e) k = 1;
        int flag = (k >= 0) ? 1 : 0;
        unsigned bal = __ballot_sync(0xffffffffu, flag);
        int pre = __popc(bal & ((1u << lane) - 1u));
        if (lane == 31) warp_sums[w] = pre + flag;
        __syncthreads();
        int wbase = 0;
        for (int i = 0; i < w; i++) wbase += warp_sums[i];
        int pos = s_base + wbase + pre;
        if (flag) {
            d_tok [e * T_TOK + pos] = t;
            d_wt  [e * T_TOK + pos] = d_topkw[2 * t + k];
            d_slot[2 * t + k]       = s_off + pos;
        }
        __syncthreads();
        if (tid == 0) {
            int tot = 0;
            for (int i = 0; i < 8; i++) tot += warp_sums[i];
            s_base += tot;
        }
        __syncthreads();
    }
    if (tid == 0) d_cnt[e] = s_base;
}

// ================= unified TF32 MMA GEMM ======================================
// EPI: 0 = write raw acc (gate pass)
//      1 = read g from C, write f2tf(silu(g)*acc) (up pass)
//      2 = down projection (EXPERT folds combine weight)
// A: EPI<2 -> d_xr (gathered when EXPERT); EPI==2 -> d_Hs / d_Hr
// B: d_Wr (+ z*N*Kd); pre-rounded, no cvt in hot loop.
template <bool EXPERT, int EPI>
__global__ __launch_bounds__(256, 2)
void gemm_k(float* __restrict__ Cout, int N, int Kd)
{
    const int z = EXPERT ? blockIdx.z : 0;
    const int M = EXPERT ? d_cnt[z] : T_TOK;
    const int off = EXPERT ? d_off[z] : 0;

    const float* A;
    float* C;
    if (EPI < 2) {
        A = d_xr;
        C = EXPERT ? (d_Hr + (size_t)off * N) : d_Hs;
    } else {
        A = EXPERT ? (d_Hr + (size_t)off * Kd) : d_Hs;
        C = EXPERT ? (d_Y + (size_t)off * N) : Cout;
    }
    const float* B = d_Wr + (size_t)z * N * Kd;

    const int row0 = blockIdx.y * BM;
    if (row0 >= M) return;
    const int col0 = blockIdx.x * BN;

    __shared__ float As[2][BM * SSTR];
    __shared__ float Bs[2][BN * SSTR];

    const int tid = threadIdx.x, lane = tid & 31, warp = tid >> 5;
    const int wm = warp >> 1, wn = warp & 1;
    const int gr = lane >> 2, gc = lane & 3;

    const int ar1 = tid >> 2, ar2 = 64 + (tid >> 2);
    const int kc  = (tid & 3) * 4;
    int r1 = row0 + ar1, r2 = row0 + ar2;
    int g1, g2;
    if (EPI < 2) {
        g1 = (r1 < M) ? (EXPERT ? d_tok[z * T_TOK + r1] : r1) : 0;
        g2 = (r2 < M) ? (EXPERT ? d_tok[z * T_TOK + r2] : r2) : 0;
    } else {
        g1 = (r1 < M) ? r1 : 0;
        g2 = (r2 < M) ? r2 : 0;
    }
    const float* Ap1 = A + (size_t)g1 * Kd + kc;
    const float* Ap2 = A + (size_t)g2 * Kd + kc;
    const int br = tid >> 2;
    const float* Bp = B + (size_t)(col0 + br) * Kd + kc;

    unsigned sa1[2], sa2[2], sb[2];
#pragma unroll
    for (int s = 0; s < 2; s++) {
        sa1[s] = smem_u32(&As[s][ar1 * SSTR + kc]);
        sa2[s] = smem_u32(&As[s][ar2 * SSTR + kc]);
        sb [s] = smem_u32(&Bs[s][br  * SSTR + kc]);
    }

    float acc[2][4][4] = {};

    const int Kt = Kd / BK;
    cp16(sa1[0], Ap1); cp16(sa2[0], Ap2); cp16(sb[0], Bp);
    cp_commit();

    for (int kt = 0; kt < Kt; kt++) {
        const int cur = kt & 1, nxt = cur ^ 1;
        if (kt + 1 < Kt) {
            const int ko = (kt + 1) * BK;
            cp16(sa1[nxt], Ap1 + ko); cp16(sa2[nxt], Ap2 + ko); cp16(sb[nxt], Bp + ko);
            cp_commit();
            cp_wait<1>();
        } else {
            cp_wait<0>();
        }
        __syncthreads();

        const float* as = As[cur];
        const float* bs = Bs[cur];
#pragma unroll
        for (int ks = 0; ks < 2; ks++) {
            const int k = ks * 8;
            unsigned afr[2][4];
#pragma unroll
            for (int mt = 0; mt < 2; mt++) {
                const int mb = wm * 32 + mt * 16;
                afr[mt][0] = __float_as_uint(as[(mb + gr    ) * SSTR + k + gc    ]);
                afr[mt][1] = __float_as_uint(as[(mb + gr + 8) * SSTR + k + gc    ]);
                afr[mt][2] = __float_as_uint(as[(mb + gr    ) * SSTR + k + gc + 4]);
                afr[mt][3] = __float_as_uint(as[(mb + gr + 8) * SSTR + k + gc + 4]);
            }
#pragma unroll
            for (int nt = 0; nt < 4; nt++) {
                const int nb = wn * 32 + nt * 8;
                unsigned bf[2];
                bf[0] = __float_as_uint(bs[(nb + gr) * SSTR + k + gc    ]);
                bf[1] = __float_as_uint(bs[(nb + gr) * SSTR + k + gc + 4]);
#pragma unroll
                for (int mt = 0; mt < 2; mt++)
                    mma1688(acc[mt][nt], afr[mt], bf);
            }
        }
        __syncthreads();
    }

    // ---- epilogue ----
#pragma unroll
    for (int mt = 0; mt < 2; mt++) {
        const int mlo = row0 + wm * 32 + mt * 16 + gr;
        const int mhi = mlo + 8;
        float slo = 1.f, shi = 1.f;
        if (EPI == 2 && EXPERT) {
            if (mlo < M) slo = d_wt[z * T_TOK + mlo];
            if (mhi < M) shi = d_wt[z * T_TOK + mhi];
        }
#pragma unroll
        for (int nt = 0; nt < 4; nt++) {
            const int n = col0 + wn * 32 + nt * 8 + gc * 2;
            if (mlo < M) {
                float2* cp = (float2*)(C + (size_t)mlo * N + n);
                float2 v;
                if (EPI == 0) {
                    v = make_float2(acc[mt][nt][0], acc[mt][nt][1]);
                } else if (EPI == 1) {
                    float2 gv = *cp;
                    v.x = __uint_as_float(f2tf(silu_mul(gv.x, acc[mt][nt][0])));
                    v.y = __uint_as_float(f2tf(silu_mul(gv.y, acc[mt][nt][1])));
                } else {
                    v = make_float2(acc[mt][nt][0] * slo, acc[mt][nt][1] * slo);
                }
                *cp = v;
            }
            if (mhi < M) {
                float2* cp = (float2*)(C + (size_t)mhi * N + n);
                float2 v;
                if (EPI == 0) {
                    v = make_float2(acc[mt][nt][2], acc[mt][nt][3]);
                } else if (EPI == 1) {
                    float2 gv = *cp;
                    v.x = __uint_as_float(f2tf(silu_mul(gv.x, acc[mt][nt][2])));
                    v.y = __uint_as_float(f2tf(silu_mul(gv.y, acc[mt][nt][3])));
                } else {
                    v = make_float2(acc[mt][nt][2] * shi, acc[mt][nt][3] * shi);
                }
                *cp = v;
            }
        }
    }
}

// ---------------- final combine ----------------------------------------------
__global__ void combine_kernel(float* __restrict__ out)
{
    int idx = blockIdx.x * blockDim.x + threadIdx.x;
    int t  = idx / (HD / 4);
    int h4 = idx % (HD / 4);
    int s0 = d_slot[2 * t], s1 = d_slot[2 * t + 1];
    float4 o = ((float4*)out)[idx];
    float4 a = ((const float4*)(d_Y + (size_t)s0 * HD))[h4];
    float4 b = ((const float4*)(d_Y + (size_t)s1 * HD))[h4];
    o.x += a.x + b.x;  o.y += a.y + b.y;  o.z += a.z + b.z;  o.w += a.w + b.w;
    ((float4*)out)[idx] = o;
}

// ---------------- launcher ---------------------------------------------------
extern "C" void kernel_launch(void* const* d_in, const int* in_sizes, int n_in,
                              void* d_out, int out_size)
{
    const float* x   = (const float*)d_in[0];
    const float* gw  = (const float*)d_in[1];
    const float* egw = (const float*)d_in[2];
    const float* euw = (const float*)d_in[3];
    const float* edw = (const float*)d_in[4];
    const float* sgw = (const float*)d_in[5];
    const float* suw = (const float*)d_in[6];
    const float* sdw = (const float*)d_in[7];
    float* out = (float*)d_out;

    const int n4x = T_TOK * HD / 4;
    const int n4s = ISD * HD / 4;
    const int n4e = NE * ID * HD / 4;

    // routing + compaction on exact fp32 inputs
    route_kernel<<<T_TOK * 32 / 256, 256>>>(x, gw);
    build_kernel<<<NE, 256>>>();

    // activations -> tf32 (RNA)
    round_k<1><<<(n4x + 255) / 256, 256>>>((const float4*)x, n4x);

    // shared expert: gate pass, then up pass (single weight scratch slot)
    round_k<0><<<(n4s + 255) / 256, 256>>>((const float4*)sgw, n4s);
    gemm_k<false, 0><<<dim3(ISD / BN, T_TOK / BM, 1), 256>>>(nullptr, ISD, HD);
    round_k<0><<<(n4s + 255) / 256, 256>>>((const float4*)suw, n4s);
    gemm_k<false, 1><<<dim3(ISD / BN, T_TOK / BM, 1), 256>>>(nullptr, ISD, HD);

    // routed experts: gate pass, then up pass (compact rows)
    round_k<0><<<(n4e + 255) / 256, 256>>>((const float4*)egw, n4e);
    gemm_k<true, 0><<<dim3(ID / BN, T_TOK / BM, NE), 256>>>(nullptr, ID, HD);
    round_k<0><<<(n4e + 255) / 256, 256>>>((const float4*)euw, n4e);
    gemm_k<true, 1><<<dim3(ID / BN, T_TOK / BM, NE), 256>>>(nullptr, ID, HD);

    // shared down -> out (full overwrite)
    round_k<0><<<(n4s + 255) / 256, 256>>>((const float4*)sdw, n4s);
    gemm_k<false, 2><<<dim3(HD / BN, T_TOK / BM, 1), 256>>>(out, HD, ISD);

    // routed down (combine weight folded) -> d_Y
    round_k<0><<<(n4e + 255) / 256, 256>>>((const float4*)edw, n4e);
    gemm_k<true, 2><<<dim3(HD / BN, T_TOK / BM, NE), 256>>>(nullptr, HD, ID);

    combine_kernel<<<(T_TOK * HD / 4) / 256, 256>>>(out);
}